// round 9
// baseline (speedup 1.0000x reference)
#include <cuda_runtime.h>
#include <cuda_bf16.h>
#include <cstdint>
#include <math.h>

// Problem shape (fixed by dataset)
#define B_ 4096
#define N_ 64
#define L_ 256
#define E_ 256

// ---------------------------------------------------------------------------
// Scratch (device globals; no allocation allowed)
// ---------------------------------------------------------------------------
__device__ float g_M[L_ * L_];       //  M = Wt^T @ Ws   [L,L]
__device__ float g_v[B_ * L_];       //  v = agent @ M^T [B,L]
__device__ float g_u[B_ * L_];       //  u = sum_n s_n * o[b,n,:]  [B,L]

// ---------------------------------------------------------------------------
// Kernel 1: M[l][lp] = sum_e Wt[e][l] * Ws[e][lp]
// grid (16,16), block (16,16)
// ---------------------------------------------------------------------------
__global__ void k_compute_M(const float* __restrict__ Wt,
                            const float* __restrict__ Ws,
                            float* __restrict__ M) {
    __shared__ float sT[16][17];
    __shared__ float sS[16][17];
    const int tx = threadIdx.x, ty = threadIdx.y;
    const int l  = blockIdx.y * 16 + ty;
    const int lp = blockIdx.x * 16 + tx;
    float acc = 0.0f;
    for (int e0 = 0; e0 < E_; e0 += 16) {
        sT[ty][tx] = Wt[(e0 + ty) * L_ + blockIdx.y * 16 + tx];
        sS[ty][tx] = Ws[(e0 + ty) * L_ + blockIdx.x * 16 + tx];
        __syncthreads();
#pragma unroll
        for (int e = 0; e < 16; e++)
            acc += sT[e][ty] * sS[e][tx];
        __syncthreads();
    }
    M[l * L_ + lp] = acc;
}

// ---------------------------------------------------------------------------
// Kernel 2/4: C[r][c] = sum_k A[r][k] * W[c][k]    (A @ W^T)
// 128 threads, BM=BN=64, BK=32, 8x4 per thread (smem-crossbar friendly:
// 12 smem floats per 32 FMA = 96 B/cyc @ 64 FMA/cyc < 128 B/cyc crossbar).
// Double-buffered smem + register prefetch; ONE sync per K-tile.
// ---------------------------------------------------------------------------
__global__ void __launch_bounds__(128)
k_gemm_awt(const float* __restrict__ A,
           const float* __restrict__ W,
           float* __restrict__ C) {
    __shared__ float As[2][32][68];
    __shared__ float Bs[2][32][68];

    const int tid  = threadIdx.x;
    const int row0 = blockIdx.y * 64;
    const int col0 = blockIdx.x * 64;
    const int trow = (tid >> 4) * 8;     // 0..56
    const int tcol = (tid & 15) * 4;     // 0..60
    const int rbase = tid >> 3;          // 0..15
    const int kv0   = (tid & 7) * 4;     // 0..28

    float acc[8][4];
#pragma unroll
    for (int i = 0; i < 8; i++)
#pragma unroll
        for (int j = 0; j < 4; j++) acc[i][j] = 0.0f;

    float4 va[4], vb[4];
#pragma unroll
    for (int p = 0; p < 4; p++) {
        const int r = rbase + p * 16;
        va[p] = *(const float4*)(A + (size_t)(row0 + r) * 256 + kv0);
        vb[p] = *(const float4*)(W + (size_t)(col0 + r) * 256 + kv0);
    }

#pragma unroll
    for (int t = 0; t < 8; t++) {
        const int buf = t & 1;
#pragma unroll
        for (int p = 0; p < 4; p++) {
            const int r = rbase + p * 16;
            As[buf][kv0 + 0][r] = va[p].x; As[buf][kv0 + 1][r] = va[p].y;
            As[buf][kv0 + 2][r] = va[p].z; As[buf][kv0 + 3][r] = va[p].w;
            Bs[buf][kv0 + 0][r] = vb[p].x; Bs[buf][kv0 + 1][r] = vb[p].y;
            Bs[buf][kv0 + 2][r] = vb[p].z; Bs[buf][kv0 + 3][r] = vb[p].w;
        }
        __syncthreads();

        if (t < 7) {
            const int k0 = (t + 1) * 32;
#pragma unroll
            for (int p = 0; p < 4; p++) {
                const int r = rbase + p * 16;
                va[p] = *(const float4*)(A + (size_t)(row0 + r) * 256 + k0 + kv0);
                vb[p] = *(const float4*)(W + (size_t)(col0 + r) * 256 + k0 + kv0);
            }
        }

#pragma unroll
        for (int k = 0; k < 32; k++) {
            float4 a0 = *(const float4*)&As[buf][k][trow];
            float4 a1 = *(const float4*)&As[buf][k][trow + 4];
            float4 bq = *(const float4*)&Bs[buf][k][tcol];
            float ar[8] = {a0.x, a0.y, a0.z, a0.w, a1.x, a1.y, a1.z, a1.w};
            float br[4] = {bq.x, bq.y, bq.z, bq.w};
#pragma unroll
            for (int i = 0; i < 8; i++)
#pragma unroll
                for (int j = 0; j < 4; j++)
                    acc[i][j] = fmaf(ar[i], br[j], acc[i][j]);
        }
        // single sync per tile: compute(t-1) precedes write(t) in program
        // order, so the top-of-loop barrier bounds buffer reuse.
    }

#pragma unroll
    for (int i = 0; i < 8; i++) {
        float4 o4 = make_float4(acc[i][0], acc[i][1], acc[i][2], acc[i][3]);
        *(float4*)(C + (size_t)(row0 + trow + i) * 256 + col0 + tcol) = o4;
    }
}

// ---------------------------------------------------------------------------
// Kernel 3: persistent register-resident fused attention.
// Grid = #SMs, 512 threads, 1 CTA/SM. No smem staging of o:
//   warp w owns n in [4w, 4w+4); lane owns l in {4*lane..+3, 4*lane+128..+131}
// Logits: register dot + shfl-reduce.  Softmax: redundant per-warp (no
// serialization).  u: register partials + 16KB cross-warp smem reduce.
// Two barriers per tile; next tile prefetched into a 2nd register set.
// ---------------------------------------------------------------------------
__global__ void __launch_bounds__(512)
k_attn3(const float* __restrict__ opp,     // [B, N, L]
        const float* __restrict__ v,       // [B, L]
        const float* __restrict__ hard,    // [B, N]
        float* __restrict__ u,             // [B, L]
        float* __restrict__ scores_out) {  // [B, N]
    __shared__ float sc[N_];
    __shared__ float upart[16 * L_];       // 16 KB

    const int tid  = threadIdx.x;
    const int warp = tid >> 5;             // 0..15
    const int lane = tid & 31;
    const int gs   = gridDim.x;

    // load one tile's slice into a register set
    auto load = [&](int bb, float4 (&o)[4][2], float4 (&vv)[2],
                    float& h0, float& h1) {
        if (bb < B_) {
            const float* ob = opp + (size_t)bb * (N_ * L_);
#pragma unroll
            for (int i = 0; i < 4; i++) {
                const int n = (warp << 2) + i;
                o[i][0] = *(const float4*)(ob + n * L_ + 4 * lane);
                o[i][1] = *(const float4*)(ob + n * L_ + 4 * lane + 128);
            }
            vv[0] = *(const float4*)(v + (size_t)bb * L_ + 4 * lane);
            vv[1] = *(const float4*)(v + (size_t)bb * L_ + 4 * lane + 128);
            h0 = hard[(size_t)bb * N_ + lane];
            h1 = hard[(size_t)bb * N_ + lane + 32];
        }
    };

    auto compute = [&](int bb, float4 (&o)[4][2], float4 (&vv)[2],
                       float h0, float h1) {
        // --- logits: per-thread partial dot over its 8 l's, shfl reduce ---
        float p[4];
#pragma unroll
        for (int i = 0; i < 4; i++) {
            float4 a0 = o[i][0], a1 = o[i][1];
            p[i] = a0.x * vv[0].x + a0.y * vv[0].y + a0.z * vv[0].z + a0.w * vv[0].w
                 + a1.x * vv[1].x + a1.y * vv[1].y + a1.z * vv[1].z + a1.w * vv[1].w;
        }
#pragma unroll
        for (int i = 0; i < 4; i++)
#pragma unroll
            for (int off = 16; off; off >>= 1)
                p[i] += __shfl_xor_sync(0xffffffffu, p[i], off);
        if (lane == 0) {
            sc[(warp << 2) + 0] = p[0];
            sc[(warp << 2) + 1] = p[1];
            sc[(warp << 2) + 2] = p[2];
            sc[(warp << 2) + 3] = p[3];
        }
        __syncthreads();                       // barrier #1

        // --- redundant per-warp softmax over 64 logits ---
        float x0 = sc[lane];
        float x1 = sc[lane + 32];
        float mx = fmaxf(x0, x1);
#pragma unroll
        for (int off = 16; off; off >>= 1)
            mx = fmaxf(mx, __shfl_xor_sync(0xffffffffu, mx, off));
        float e0 = expf(x0 - mx);
        float e1 = expf(x1 - mx);
        float ssum = e0 + e1;
#pragma unroll
        for (int off = 16; off; off >>= 1)
            ssum += __shfl_xor_sync(0xffffffffu, ssum, off);
        const float inv = 1.0f / ssum;
        const float s0 = e0 * inv * h0;
        const float s1 = e1 * inv * h1;
        if (warp == 0) {
            scores_out[(size_t)bb * N_ + lane]      = s0;
            scores_out[(size_t)bb * N_ + lane + 32] = s1;
        }

        // --- u partials from registers; scores via shfl ---
        float4 u0 = make_float4(0.f, 0.f, 0.f, 0.f);
        float4 u1 = make_float4(0.f, 0.f, 0.f, 0.f);
        const float smine = (warp < 8) ? s0 : s1;   // holds s(n) for n=lane(+32)
#pragma unroll
        for (int i = 0; i < 4; i++) {
            const int n = (warp << 2) + i;
            const float sn = __shfl_sync(0xffffffffu, smine, n & 31);
            u0.x = fmaf(sn, o[i][0].x, u0.x);
            u0.y = fmaf(sn, o[i][0].y, u0.y);
            u0.z = fmaf(sn, o[i][0].z, u0.z);
            u0.w = fmaf(sn, o[i][0].w, u0.w);
            u1.x = fmaf(sn, o[i][1].x, u1.x);
            u1.y = fmaf(sn, o[i][1].y, u1.y);
            u1.z = fmaf(sn, o[i][1].z, u1.z);
            u1.w = fmaf(sn, o[i][1].w, u1.w);
        }
        float* up = upart + warp * L_;
        *(float4*)(up + 4 * lane)       = u0;
        *(float4*)(up + 4 * lane + 128) = u1;
        __syncthreads();                       // barrier #2

        if (tid < L_) {
            float a = 0.0f;
#pragma unroll
            for (int w = 0; w < 16; w++)
                a += upart[w * L_ + tid];
            u[(size_t)bb * L_ + tid] = a;
        }
        // next tile's sc/upart writes are fenced by barriers #1/#2 above
    };

    float4 oA[4][2], oB[4][2];
    float4 vA[2], vB[2];
    float hA0 = 0.f, hA1 = 0.f, hB0 = 0.f, hB1 = 0.f;

    int b = blockIdx.x;
    load(b, oA, vA, hA0, hA1);
    while (b < B_) {
        load(b + gs, oB, vB, hB0, hB1);    // prefetch next tile
        compute(b, oA, vA, hA0, hA1);
        b += gs;
        if (b >= B_) break;
        load(b + gs, oA, vA, hA0, hA1);    // prefetch next-next tile
        compute(b, oB, vB, hB0, hB1);
        b += gs;
    }
}

// ---------------------------------------------------------------------------
// Launch
// ---------------------------------------------------------------------------
extern "C" void kernel_launch(void* const* d_in, const int* in_sizes, int n_in,
                              void* d_out, int out_size) {
    const float* agent = (const float*)d_in[0];   // [B, L]
    const float* opp   = (const float*)d_in[1];   // [B, N, L]
    const float* hard  = (const float*)d_in[2];   // [B, N]
    const float* Ws    = (const float*)d_in[3];   // [E, L]
    const float* Wt    = (const float*)d_in[4];   // [E, L]
    const float* Wc    = (const float*)d_in[5];   // [E, L]

    float* out        = (float*)d_out;
    float* result_out = out;                      // [B, E]
    float* scores_out = out + (size_t)B_ * E_;    // [B, N]

    float *dM, *dv, *du;
    cudaGetSymbolAddress((void**)&dM, g_M);
    cudaGetSymbolAddress((void**)&dv, g_v);
    cudaGetSymbolAddress((void**)&du, g_u);

    int dev = 0, nsm = 148;
    cudaGetDevice(&dev);
    cudaDeviceGetAttribute(&nsm, cudaDevAttrMultiProcessorCount, dev);

    // 1. M = Wt^T @ Ws
    k_compute_M<<<dim3(L_ / 16, L_ / 16), dim3(16, 16)>>>(Wt, Ws, dM);

    // 2. v = agent @ M^T
    k_gemm_awt<<<dim3(L_ / 64, B_ / 64), 128>>>(agent, dM, dv);

    // 3. persistent register-resident attention: one HBM pass over opp
    k_attn3<<<nsm, 512>>>(opp, dv, hard, du, scores_out);

    // 4. result = u @ Wc^T
    k_gemm_awt<<<dim3(E_ / 64, B_ / 64), 128>>>(du, Wc, result_out);
}

// round 10
// speedup vs baseline: 1.3312x; 1.3312x over previous
#include <cuda_runtime.h>
#include <cuda_bf16.h>
#include <cstdint>
#include <math.h>

// Problem shape (fixed by dataset)
#define B_ 4096
#define N_ 64
#define L_ 256
#define E_ 256

// ---------------------------------------------------------------------------
// Scratch (device globals; no allocation allowed)
// ---------------------------------------------------------------------------
__device__ float g_M[L_ * L_];       //  M = Wt^T @ Ws   [L,L]
__device__ float g_v[B_ * L_];       //  v = agent @ M^T [B,L]
__device__ float g_u[B_ * L_];       //  u = sum_n s_n * o[b,n,:]  [B,L]

// ---------------------------------------------------------------------------
// Kernel 1: M[l][lp] = sum_e Wt[e][l] * Ws[e][lp]
// grid (16,16), block (16,16)
// ---------------------------------------------------------------------------
__global__ void k_compute_M(const float* __restrict__ Wt,
                            const float* __restrict__ Ws,
                            float* __restrict__ M) {
    __shared__ float sT[16][17];
    __shared__ float sS[16][17];
    const int tx = threadIdx.x, ty = threadIdx.y;
    const int l  = blockIdx.y * 16 + ty;
    const int lp = blockIdx.x * 16 + tx;
    float acc = 0.0f;
    for (int e0 = 0; e0 < E_; e0 += 16) {
        sT[ty][tx] = Wt[(e0 + ty) * L_ + blockIdx.y * 16 + tx];
        sS[ty][tx] = Ws[(e0 + ty) * L_ + blockIdx.x * 16 + tx];
        __syncthreads();
#pragma unroll
        for (int e = 0; e < 16; e++)
            acc += sT[e][ty] * sS[e][tx];
        __syncthreads();
    }
    M[l * L_ + lp] = acc;
}

// ---------------------------------------------------------------------------
// Kernel 2/4: C[r][c] = sum_k A[r][k] * W[c][k]    (A @ W^T)
// R8-proven config: 256 threads, BM=BN=64, BK=32, 4x4 per thread.
// Double-buffered smem + register prefetch; ONE sync per K-tile.
// ---------------------------------------------------------------------------
#define BM 64
#define BN 64
#define BK 32
__global__ void __launch_bounds__(256)
k_gemm_awt(const float* __restrict__ A,
           const float* __restrict__ W,
           float* __restrict__ C) {
    __shared__ float As[2][BK][BM + 4];
    __shared__ float Bs[2][BK][BN + 4];

    const int tid  = threadIdx.x;
    const int row0 = blockIdx.y * BM;
    const int col0 = blockIdx.x * BN;
    const int trow = (tid >> 4) * 4;
    const int tcol = (tid & 15) * 4;

    // per-thread load coordinates (fixed across tiles)
    const int r0 = (tid)       >> 3;        // 0..31
    const int r1 = (tid + 256) >> 3;        // 32..63
    const int kv0 = (tid & 7) * 4;

    float acc[4][4];
#pragma unroll
    for (int i = 0; i < 4; i++)
#pragma unroll
        for (int j = 0; j < 4; j++) acc[i][j] = 0.0f;

    // prologue load of tile 0
    float4 va0 = *(const float4*)(A + (size_t)(row0 + r0) * 256 + 0 + kv0);
    float4 va1 = *(const float4*)(A + (size_t)(row0 + r1) * 256 + 0 + kv0);
    float4 vb0 = *(const float4*)(W + (size_t)(col0 + r0) * 256 + 0 + kv0);
    float4 vb1 = *(const float4*)(W + (size_t)(col0 + r1) * 256 + 0 + kv0);

#pragma unroll
    for (int t = 0; t < 8; t++) {
        const int buf = t & 1;
        // stage current tile
        As[buf][kv0 + 0][r0] = va0.x; As[buf][kv0 + 1][r0] = va0.y;
        As[buf][kv0 + 2][r0] = va0.z; As[buf][kv0 + 3][r0] = va0.w;
        As[buf][kv0 + 0][r1] = va1.x; As[buf][kv0 + 1][r1] = va1.y;
        As[buf][kv0 + 2][r1] = va1.z; As[buf][kv0 + 3][r1] = va1.w;
        Bs[buf][kv0 + 0][r0] = vb0.x; Bs[buf][kv0 + 1][r0] = vb0.y;
        Bs[buf][kv0 + 2][r0] = vb0.z; Bs[buf][kv0 + 3][r0] = vb0.w;
        Bs[buf][kv0 + 0][r1] = vb1.x; Bs[buf][kv0 + 1][r1] = vb1.y;
        Bs[buf][kv0 + 2][r1] = vb1.z; Bs[buf][kv0 + 3][r1] = vb1.w;
        __syncthreads();

        // prefetch next tile while computing this one
        if (t < 7) {
            const int k0 = (t + 1) * BK;
            va0 = *(const float4*)(A + (size_t)(row0 + r0) * 256 + k0 + kv0);
            va1 = *(const float4*)(A + (size_t)(row0 + r1) * 256 + k0 + kv0);
            vb0 = *(const float4*)(W + (size_t)(col0 + r0) * 256 + k0 + kv0);
            vb1 = *(const float4*)(W + (size_t)(col0 + r1) * 256 + k0 + kv0);
        }

#pragma unroll
        for (int k = 0; k < BK; k++) {
            float4 av = *(const float4*)&As[buf][k][trow];
            float4 bv = *(const float4*)&Bs[buf][k][tcol];
            float a[4] = {av.x, av.y, av.z, av.w};
            float b[4] = {bv.x, bv.y, bv.z, bv.w};
#pragma unroll
            for (int i = 0; i < 4; i++)
#pragma unroll
                for (int j = 0; j < 4; j++)
                    acc[i][j] = fmaf(a[i], b[j], acc[i][j]);
        }
        // single sync per tile: compute(t-1) precedes write(t) in program
        // order, so the top-of-loop barrier bounds buffer reuse.
    }

#pragma unroll
    for (int i = 0; i < 4; i++) {
        float4 o4 = make_float4(acc[i][0], acc[i][1], acc[i][2], acc[i][3]);
        *(float4*)(C + (size_t)(row0 + trow + i) * 256 + col0 + tcol) = o4;
    }
}

// ---------------------------------------------------------------------------
// Kernel 3: persistent register-resident fused attention (R9-proven, ~32us).
// Grid = #SMs, 512 threads, 1 CTA/SM. No smem staging of o:
//   warp w owns n in [4w, 4w+4); lane owns l in {4*lane..+3, 4*lane+128..+131}
// Logits: register dot + shfl-reduce.  Softmax: redundant per-warp (no
// serialization).  u: register partials + 16KB cross-warp smem reduce.
// Two barriers per tile; next tile prefetched into a 2nd register set.
// ---------------------------------------------------------------------------
__global__ void __launch_bounds__(512)
k_attn3(const float* __restrict__ opp,     // [B, N, L]
        const float* __restrict__ v,       // [B, L]
        const float* __restrict__ hard,    // [B, N]
        float* __restrict__ u,             // [B, L]
        float* __restrict__ scores_out) {  // [B, N]
    __shared__ float sc[N_];
    __shared__ float upart[16 * L_];       // 16 KB

    const int tid  = threadIdx.x;
    const int warp = tid >> 5;             // 0..15
    const int lane = tid & 31;
    const int gs   = gridDim.x;

    // load one tile's slice into a register set
    auto load = [&](int bb, float4 (&o)[4][2], float4 (&vv)[2],
                    float& h0, float& h1) {
        if (bb < B_) {
            const float* ob = opp + (size_t)bb * (N_ * L_);
#pragma unroll
            for (int i = 0; i < 4; i++) {
                const int n = (warp << 2) + i;
                o[i][0] = *(const float4*)(ob + n * L_ + 4 * lane);
                o[i][1] = *(const float4*)(ob + n * L_ + 4 * lane + 128);
            }
            vv[0] = *(const float4*)(v + (size_t)bb * L_ + 4 * lane);
            vv[1] = *(const float4*)(v + (size_t)bb * L_ + 4 * lane + 128);
            h0 = hard[(size_t)bb * N_ + lane];
            h1 = hard[(size_t)bb * N_ + lane + 32];
        }
    };

    auto compute = [&](int bb, float4 (&o)[4][2], float4 (&vv)[2],
                       float h0, float h1) {
        // --- logits: per-thread partial dot over its 8 l's, shfl reduce ---
        float p[4];
#pragma unroll
        for (int i = 0; i < 4; i++) {
            float4 a0 = o[i][0], a1 = o[i][1];
            p[i] = a0.x * vv[0].x + a0.y * vv[0].y + a0.z * vv[0].z + a0.w * vv[0].w
                 + a1.x * vv[1].x + a1.y * vv[1].y + a1.z * vv[1].z + a1.w * vv[1].w;
        }
#pragma unroll
        for (int i = 0; i < 4; i++)
#pragma unroll
            for (int off = 16; off; off >>= 1)
                p[i] += __shfl_xor_sync(0xffffffffu, p[i], off);
        if (lane == 0) {
            sc[(warp << 2) + 0] = p[0];
            sc[(warp << 2) + 1] = p[1];
            sc[(warp << 2) + 2] = p[2];
            sc[(warp << 2) + 3] = p[3];
        }
        __syncthreads();                       // barrier #1

        // --- redundant per-warp softmax over 64 logits ---
        float x0 = sc[lane];
        float x1 = sc[lane + 32];
        float mx = fmaxf(x0, x1);
#pragma unroll
        for (int off = 16; off; off >>= 1)
            mx = fmaxf(mx, __shfl_xor_sync(0xffffffffu, mx, off));
        float e0 = expf(x0 - mx);
        float e1 = expf(x1 - mx);
        float ssum = e0 + e1;
#pragma unroll
        for (int off = 16; off; off >>= 1)
            ssum += __shfl_xor_sync(0xffffffffu, ssum, off);
        const float inv = 1.0f / ssum;
        const float s0 = e0 * inv * h0;
        const float s1 = e1 * inv * h1;
        if (warp == 0) {
            scores_out[(size_t)bb * N_ + lane]      = s0;
            scores_out[(size_t)bb * N_ + lane + 32] = s1;
        }

        // --- u partials from registers; scores via shfl ---
        float4 u0 = make_float4(0.f, 0.f, 0.f, 0.f);
        float4 u1 = make_float4(0.f, 0.f, 0.f, 0.f);
        const float smine = (warp < 8) ? s0 : s1;   // holds s(n) for n=lane(+32)
#pragma unroll
        for (int i = 0; i < 4; i++) {
            const int n = (warp << 2) + i;
            const float sn = __shfl_sync(0xffffffffu, smine, n & 31);
            u0.x = fmaf(sn, o[i][0].x, u0.x);
            u0.y = fmaf(sn, o[i][0].y, u0.y);
            u0.z = fmaf(sn, o[i][0].z, u0.z);
            u0.w = fmaf(sn, o[i][0].w, u0.w);
            u1.x = fmaf(sn, o[i][1].x, u1.x);
            u1.y = fmaf(sn, o[i][1].y, u1.y);
            u1.z = fmaf(sn, o[i][1].z, u1.z);
            u1.w = fmaf(sn, o[i][1].w, u1.w);
        }
        float* up = upart + warp * L_;
        *(float4*)(up + 4 * lane)       = u0;
        *(float4*)(up + 4 * lane + 128) = u1;
        __syncthreads();                       // barrier #2

        if (tid < L_) {
            float a = 0.0f;
#pragma unroll
            for (int w = 0; w < 16; w++)
                a += upart[w * L_ + tid];
            u[(size_t)bb * L_ + tid] = a;
        }
        // next tile's sc/upart writes are fenced by barriers #1/#2 above
    };

    float4 oA[4][2], oB[4][2];
    float4 vA[2], vB[2];
    float hA0 = 0.f, hA1 = 0.f, hB0 = 0.f, hB1 = 0.f;

    int b = blockIdx.x;
    load(b, oA, vA, hA0, hA1);
    while (b < B_) {
        load(b + gs, oB, vB, hB0, hB1);    // prefetch next tile
        compute(b, oA, vA, hA0, hA1);
        b += gs;
        if (b >= B_) break;
        load(b + gs, oA, vA, hA0, hA1);    // prefetch next-next tile
        compute(b, oB, vB, hB0, hB1);
        b += gs;
    }
}

// ---------------------------------------------------------------------------
// Launch
// ---------------------------------------------------------------------------
extern "C" void kernel_launch(void* const* d_in, const int* in_sizes, int n_in,
                              void* d_out, int out_size) {
    const float* agent = (const float*)d_in[0];   // [B, L]
    const float* opp   = (const float*)d_in[1];   // [B, N, L]
    const float* hard  = (const float*)d_in[2];   // [B, N]
    const float* Ws    = (const float*)d_in[3];   // [E, L]
    const float* Wt    = (const float*)d_in[4];   // [E, L]
    const float* Wc    = (const float*)d_in[5];   // [E, L]

    float* out        = (float*)d_out;
    float* result_out = out;                      // [B, E]
    float* scores_out = out + (size_t)B_ * E_;    // [B, N]

    float *dM, *dv, *du;
    cudaGetSymbolAddress((void**)&dM, g_M);
    cudaGetSymbolAddress((void**)&dv, g_v);
    cudaGetSymbolAddress((void**)&du, g_u);

    int dev = 0, nsm = 148;
    cudaGetDevice(&dev);
    cudaDeviceGetAttribute(&nsm, cudaDevAttrMultiProcessorCount, dev);

    // 1. M = Wt^T @ Ws
    k_compute_M<<<dim3(L_ / 16, L_ / 16), dim3(16, 16)>>>(Wt, Ws, dM);

    // 2. v = agent @ M^T
    k_gemm_awt<<<dim3(L_ / BN, B_ / BM), 256>>>(agent, dM, dv);

    // 3. persistent register-resident attention: one HBM pass over opp
    k_attn3<<<nsm, 512>>>(opp, dv, hard, du, scores_out);

    // 4. result = u @ Wc^T
    k_gemm_awt<<<dim3(E_ / BN, B_ / BM), 256>>>(du, Wc, result_out);
}

// round 11
// speedup vs baseline: 1.3370x; 1.0043x over previous
#include <cuda_runtime.h>
#include <cuda_bf16.h>
#include <cstdint>
#include <math.h>

// Problem shape (fixed by dataset)
#define B_ 4096
#define N_ 64
#define L_ 256
#define E_ 256

// ---------------------------------------------------------------------------
// Scratch (device globals; no allocation allowed)
// ---------------------------------------------------------------------------
__device__ float g_M[L_ * L_];       //  M = Wt^T @ Ws   [L,L]
__device__ float g_v[B_ * L_];       //  v = agent @ M^T [B,L]
__device__ float g_u[B_ * L_];       //  u = sum_n s_n * o[b,n,:]  [B,L]

// ---------------------------------------------------------------------------
// Kernel 1: M[l][lp] = sum_e Wt[e][l] * Ws[e][lp]
// grid (16,16), block (16,16)
// ---------------------------------------------------------------------------
__global__ void k_compute_M(const float* __restrict__ Wt,
                            const float* __restrict__ Ws,
                            float* __restrict__ M) {
    __shared__ float sT[16][17];
    __shared__ float sS[16][17];
    const int tx = threadIdx.x, ty = threadIdx.y;
    const int l  = blockIdx.y * 16 + ty;
    const int lp = blockIdx.x * 16 + tx;
    float acc = 0.0f;
    for (int e0 = 0; e0 < E_; e0 += 16) {
        sT[ty][tx] = Wt[(e0 + ty) * L_ + blockIdx.y * 16 + tx];
        sS[ty][tx] = Ws[(e0 + ty) * L_ + blockIdx.x * 16 + tx];
        __syncthreads();
#pragma unroll
        for (int e = 0; e < 16; e++)
            acc += sT[e][ty] * sS[e][tx];
        __syncthreads();
    }
    M[l * L_ + lp] = acc;
}

// ---------------------------------------------------------------------------
// Kernel 2/4: C[r][c] = sum_k A[r][k] * W[c][k]    (A @ W^T)
// R8-proven config: 256 threads, BM=BN=64, BK=32, 4x4 per thread.
// Double-buffered smem + register prefetch; ONE sync per K-tile.
// ---------------------------------------------------------------------------
#define BM 64
#define BN 64
#define BK 32
__global__ void __launch_bounds__(256)
k_gemm_awt(const float* __restrict__ A,
           const float* __restrict__ W,
           float* __restrict__ C) {
    __shared__ float As[2][BK][BM + 4];
    __shared__ float Bs[2][BK][BN + 4];

    const int tid  = threadIdx.x;
    const int row0 = blockIdx.y * BM;
    const int col0 = blockIdx.x * BN;
    const int trow = (tid >> 4) * 4;
    const int tcol = (tid & 15) * 4;

    // per-thread load coordinates (fixed across tiles)
    const int r0 = (tid)       >> 3;        // 0..31
    const int r1 = (tid + 256) >> 3;        // 32..63
    const int kv0 = (tid & 7) * 4;

    float acc[4][4];
#pragma unroll
    for (int i = 0; i < 4; i++)
#pragma unroll
        for (int j = 0; j < 4; j++) acc[i][j] = 0.0f;

    // prologue load of tile 0
    float4 va0 = *(const float4*)(A + (size_t)(row0 + r0) * 256 + 0 + kv0);
    float4 va1 = *(const float4*)(A + (size_t)(row0 + r1) * 256 + 0 + kv0);
    float4 vb0 = *(const float4*)(W + (size_t)(col0 + r0) * 256 + 0 + kv0);
    float4 vb1 = *(const float4*)(W + (size_t)(col0 + r1) * 256 + 0 + kv0);

#pragma unroll
    for (int t = 0; t < 8; t++) {
        const int buf = t & 1;
        // stage current tile
        As[buf][kv0 + 0][r0] = va0.x; As[buf][kv0 + 1][r0] = va0.y;
        As[buf][kv0 + 2][r0] = va0.z; As[buf][kv0 + 3][r0] = va0.w;
        As[buf][kv0 + 0][r1] = va1.x; As[buf][kv0 + 1][r1] = va1.y;
        As[buf][kv0 + 2][r1] = va1.z; As[buf][kv0 + 3][r1] = va1.w;
        Bs[buf][kv0 + 0][r0] = vb0.x; Bs[buf][kv0 + 1][r0] = vb0.y;
        Bs[buf][kv0 + 2][r0] = vb0.z; Bs[buf][kv0 + 3][r0] = vb0.w;
        Bs[buf][kv0 + 0][r1] = vb1.x; Bs[buf][kv0 + 1][r1] = vb1.y;
        Bs[buf][kv0 + 2][r1] = vb1.z; Bs[buf][kv0 + 3][r1] = vb1.w;
        __syncthreads();

        // prefetch next tile while computing this one
        if (t < 7) {
            const int k0 = (t + 1) * BK;
            va0 = *(const float4*)(A + (size_t)(row0 + r0) * 256 + k0 + kv0);
            va1 = *(const float4*)(A + (size_t)(row0 + r1) * 256 + k0 + kv0);
            vb0 = *(const float4*)(W + (size_t)(col0 + r0) * 256 + k0 + kv0);
            vb1 = *(const float4*)(W + (size_t)(col0 + r1) * 256 + k0 + kv0);
        }

#pragma unroll
        for (int k = 0; k < BK; k++) {
            float4 av = *(const float4*)&As[buf][k][trow];
            float4 bv = *(const float4*)&Bs[buf][k][tcol];
            float a[4] = {av.x, av.y, av.z, av.w};
            float b[4] = {bv.x, bv.y, bv.z, bv.w};
#pragma unroll
            for (int i = 0; i < 4; i++)
#pragma unroll
                for (int j = 0; j < 4; j++)
                    acc[i][j] = fmaf(a[i], b[j], acc[i][j]);
        }
        // single sync per tile: compute(t-1) precedes write(t) in program
        // order, so the top-of-loop barrier bounds buffer reuse.
    }

#pragma unroll
    for (int i = 0; i < 4; i++) {
        float4 o4 = make_float4(acc[i][0], acc[i][1], acc[i][2], acc[i][3]);
        *(float4*)(C + (size_t)(row0 + trow + i) * 256 + col0 + tcol) = o4;
    }
}

// ---------------------------------------------------------------------------
// Kernel 3: persistent register-resident fused attention (R9-proven, ~32us).
// Grid = #SMs, 512 threads, 1 CTA/SM. No smem staging of o:
//   warp w owns n in [4w, 4w+4); lane owns l in {4*lane..+3, 4*lane+128..+131}
// Logits: register dot + shfl-reduce.  Softmax: redundant per-warp (no
// serialization).  u: register partials + 16KB cross-warp smem reduce.
// Two barriers per tile; next tile prefetched into a 2nd register set.
// ---------------------------------------------------------------------------
__global__ void __launch_bounds__(512)
k_attn3(const float* __restrict__ opp,     // [B, N, L]
        const float* __restrict__ v,       // [B, L]
        const float* __restrict__ hard,    // [B, N]
        float* __restrict__ u,             // [B, L]
        float* __restrict__ scores_out) {  // [B, N]
    __shared__ float sc[N_];
    __shared__ float upart[16 * L_];       // 16 KB

    const int tid  = threadIdx.x;
    const int warp = tid >> 5;             // 0..15
    const int lane = tid & 31;
    const int gs   = gridDim.x;

    // load one tile's slice into a register set
    auto load = [&](int bb, float4 (&o)[4][2], float4 (&vv)[2],
                    float& h0, float& h1) {
        if (bb < B_) {
            const float* ob = opp + (size_t)bb * (N_ * L_);
#pragma unroll
            for (int i = 0; i < 4; i++) {
                const int n = (warp << 2) + i;
                o[i][0] = *(const float4*)(ob + n * L_ + 4 * lane);
                o[i][1] = *(const float4*)(ob + n * L_ + 4 * lane + 128);
            }
            vv[0] = *(const float4*)(v + (size_t)bb * L_ + 4 * lane);
            vv[1] = *(const float4*)(v + (size_t)bb * L_ + 4 * lane + 128);
            h0 = hard[(size_t)bb * N_ + lane];
            h1 = hard[(size_t)bb * N_ + lane + 32];
        }
    };

    auto compute = [&](int bb, float4 (&o)[4][2], float4 (&vv)[2],
                       float h0, float h1) {
        // --- logits: per-thread partial dot over its 8 l's, shfl reduce ---
        float p[4];
#pragma unroll
        for (int i = 0; i < 4; i++) {
            float4 a0 = o[i][0], a1 = o[i][1];
            p[i] = a0.x * vv[0].x + a0.y * vv[0].y + a0.z * vv[0].z + a0.w * vv[0].w
                 + a1.x * vv[1].x + a1.y * vv[1].y + a1.z * vv[1].z + a1.w * vv[1].w;
        }
#pragma unroll
        for (int i = 0; i < 4; i++)
#pragma unroll
            for (int off = 16; off; off >>= 1)
                p[i] += __shfl_xor_sync(0xffffffffu, p[i], off);
        if (lane == 0) {
            sc[(warp << 2) + 0] = p[0];
            sc[(warp << 2) + 1] = p[1];
            sc[(warp << 2) + 2] = p[2];
            sc[(warp << 2) + 3] = p[3];
        }
        __syncthreads();                       // barrier #1

        // --- redundant per-warp softmax over 64 logits ---
        float x0 = sc[lane];
        float x1 = sc[lane + 32];
        float mx = fmaxf(x0, x1);
#pragma unroll
        for (int off = 16; off; off >>= 1)
            mx = fmaxf(mx, __shfl_xor_sync(0xffffffffu, mx, off));
        float e0 = expf(x0 - mx);
        float e1 = expf(x1 - mx);
        float ssum = e0 + e1;
#pragma unroll
        for (int off = 16; off; off >>= 1)
            ssum += __shfl_xor_sync(0xffffffffu, ssum, off);
        const float inv = 1.0f / ssum;
        const float s0 = e0 * inv * h0;
        const float s1 = e1 * inv * h1;
        if (warp == 0) {
            scores_out[(size_t)bb * N_ + lane]      = s0;
            scores_out[(size_t)bb * N_ + lane + 32] = s1;
        }

        // --- u partials from registers; scores via shfl ---
        float4 u0 = make_float4(0.f, 0.f, 0.f, 0.f);
        float4 u1 = make_float4(0.f, 0.f, 0.f, 0.f);
        const float smine = (warp < 8) ? s0 : s1;   // holds s(n) for n=lane(+32)
#pragma unroll
        for (int i = 0; i < 4; i++) {
            const int n = (warp << 2) + i;
            const float sn = __shfl_sync(0xffffffffu, smine, n & 31);
            u0.x = fmaf(sn, o[i][0].x, u0.x);
            u0.y = fmaf(sn, o[i][0].y, u0.y);
            u0.z = fmaf(sn, o[i][0].z, u0.z);
            u0.w = fmaf(sn, o[i][0].w, u0.w);
            u1.x = fmaf(sn, o[i][1].x, u1.x);
            u1.y = fmaf(sn, o[i][1].y, u1.y);
            u1.z = fmaf(sn, o[i][1].z, u1.z);
            u1.w = fmaf(sn, o[i][1].w, u1.w);
        }
        float* up = upart + warp * L_;
        *(float4*)(up + 4 * lane)       = u0;
        *(float4*)(up + 4 * lane + 128) = u1;
        __syncthreads();                       // barrier #2

        if (tid < L_) {
            float a = 0.0f;
#pragma unroll
            for (int w = 0; w < 16; w++)
                a += upart[w * L_ + tid];
            u[(size_t)bb * L_ + tid] = a;
        }
        // next tile's sc/upart writes are fenced by barriers #1/#2 above
    };

    float4 oA[4][2], oB[4][2];
    float4 vA[2], vB[2];
    float hA0 = 0.f, hA1 = 0.f, hB0 = 0.f, hB1 = 0.f;

    int b = blockIdx.x;
    load(b, oA, vA, hA0, hA1);
    while (b < B_) {
        load(b + gs, oB, vB, hB0, hB1);    // prefetch next tile
        compute(b, oA, vA, hA0, hA1);
        b += gs;
        if (b >= B_) break;
        load(b + gs, oA, vA, hA0, hA1);    // prefetch next-next tile
        compute(b, oB, vB, hB0, hB1);
        b += gs;
    }
}

// ---------------------------------------------------------------------------
// Launch
// ---------------------------------------------------------------------------
extern "C" void kernel_launch(void* const* d_in, const int* in_sizes, int n_in,
                              void* d_out, int out_size) {
    const float* agent = (const float*)d_in[0];   // [B, L]
    const float* opp   = (const float*)d_in[1];   // [B, N, L]
    const float* hard  = (const float*)d_in[2];   // [B, N]
    const float* Ws    = (const float*)d_in[3];   // [E, L]
    const float* Wt    = (const float*)d_in[4];   // [E, L]
    const float* Wc    = (const float*)d_in[5];   // [E, L]

    float* out        = (float*)d_out;
    float* result_out = out;                      // [B, E]
    float* scores_out = out + (size_t)B_ * E_;    // [B, N]

    float *dM, *dv, *du;
    cudaGetSymbolAddress((void**)&dM, g_M);
    cudaGetSymbolAddress((void**)&dv, g_v);
    cudaGetSymbolAddress((void**)&du, g_u);

    int dev = 0, nsm = 148;
    cudaGetDevice(&dev);
    cudaDeviceGetAttribute(&nsm, cudaDevAttrMultiProcessorCount, dev);

    // 1. M = Wt^T @ Ws
    k_compute_M<<<dim3(L_ / 16, L_ / 16), dim3(16, 16)>>>(Wt, Ws, dM);

    // 2. v = agent @ M^T
    k_gemm_awt<<<dim3(L_ / BN, B_ / BM), 256>>>(agent, dM, dv);

    // 3. persistent register-resident attention: one HBM pass over opp
    k_attn3<<<nsm, 512>>>(opp, dv, hard, du, scores_out);

    // 4. result = u @ Wc^T
    k_gemm_awt<<<dim3(E_ / BN, B_ / BM), 256>>>(du, Wc, result_out);
}